// round 1
// baseline (speedup 1.0000x reference)
#include <cuda_runtime.h>

// Problem constants (fixed shapes from reference setup_inputs)
constexpr int B_  = 32;
constexpr int C_  = 256;
constexpr int N_  = 4608;         // H*W = 96*48
constexpr int N4  = N_ / 4;       // 1152 float4 per (b,c) row

constexpr int K1_THREADS = 128;
constexpr int TILE_N     = K1_THREADS * 4;   // 512 n per block
constexpr int NT1        = N_ / TILE_N;      // 9 tiles per batch

constexpr int K3_THREADS = 384;              // 1152 / 3 float4 per thread

// Scratch (allocation-free rule: __device__ globals)
__device__ float g_theta[B_ * N_];
__device__ float g_partial[B_ * NT1];
__device__ float g_s[B_];
__device__ float g_acoef[C_];
__device__ float g_dcoef[C_];

// ---------------------------------------------------------------------------
// Kernel 1: per (b,n) channel dots. g/theta/phi = w · x[b,:,n] + bias.
// Stores theta row; block-reduces sum(phi*g) into g_partial.
// ---------------------------------------------------------------------------
__global__ __launch_bounds__(K1_THREADS)
void k1_dots(const float* __restrict__ x,
             const float* __restrict__ gw, const float* __restrict__ gb,
             const float* __restrict__ tw, const float* __restrict__ tb,
             const float* __restrict__ pw, const float* __restrict__ pb)
{
    __shared__ float swt[3 * C_];
    const int tid = threadIdx.x;
    for (int i = tid; i < C_; i += K1_THREADS) {
        swt[i]          = gw[i];
        swt[C_ + i]     = tw[i];
        swt[2 * C_ + i] = pw[i];
    }
    __syncthreads();

    const int t = blockIdx.x;          // n-tile
    const int b = blockIdx.y;          // batch
    const int i4 = (t * TILE_N) / 4 + tid;   // float4 index within a row

    const float4* xr = reinterpret_cast<const float4*>(x)
                       + (size_t)b * C_ * N4 + i4;

    float4 ga = make_float4(0.f, 0.f, 0.f, 0.f);
    float4 ta = make_float4(0.f, 0.f, 0.f, 0.f);
    float4 pa = make_float4(0.f, 0.f, 0.f, 0.f);

    #pragma unroll 8
    for (int c = 0; c < C_; c++) {
        const float4 xv = __ldg(xr + (size_t)c * N4);
        const float w0 = swt[c];
        const float w1 = swt[C_ + c];
        const float w2 = swt[2 * C_ + c];
        ga.x = fmaf(w0, xv.x, ga.x); ga.y = fmaf(w0, xv.y, ga.y);
        ga.z = fmaf(w0, xv.z, ga.z); ga.w = fmaf(w0, xv.w, ga.w);
        ta.x = fmaf(w1, xv.x, ta.x); ta.y = fmaf(w1, xv.y, ta.y);
        ta.z = fmaf(w1, xv.z, ta.z); ta.w = fmaf(w1, xv.w, ta.w);
        pa.x = fmaf(w2, xv.x, pa.x); pa.y = fmaf(w2, xv.y, pa.y);
        pa.z = fmaf(w2, xv.z, pa.z); pa.w = fmaf(w2, xv.w, pa.w);
    }

    const float gb0 = __ldg(gb), tb0 = __ldg(tb), pb0 = __ldg(pb);

    // sum over this thread's 4 n of phi*g
    float pg = (pa.x + pb0) * (ga.x + gb0)
             + (pa.y + pb0) * (ga.y + gb0)
             + (pa.z + pb0) * (ga.z + gb0)
             + (pa.w + pb0) * (ga.w + gb0);

    // store theta + bias
    reinterpret_cast<float4*>(g_theta)[(size_t)b * N4 + i4] =
        make_float4(ta.x + tb0, ta.y + tb0, ta.z + tb0, ta.w + tb0);

    // block reduce pg
    #pragma unroll
    for (int off = 16; off > 0; off >>= 1)
        pg += __shfl_xor_sync(0xffffffffu, pg, off);

    __shared__ float red[K1_THREADS / 32];
    if ((tid & 31) == 0) red[tid >> 5] = pg;
    __syncthreads();
    if (tid == 0) {
        float s = 0.f;
        #pragma unroll
        for (int w = 0; w < K1_THREADS / 32; w++) s += red[w];
        g_partial[b * NT1 + t] = s;
    }
}

// ---------------------------------------------------------------------------
// Kernel 2 (tiny): reduce partials into s[b]; fold BN+W into a[c], d[c].
// ---------------------------------------------------------------------------
__global__ void k2_coeffs(const float* __restrict__ Ww, const float* __restrict__ Wb,
                          const float* __restrict__ gamma, const float* __restrict__ beta,
                          const float* __restrict__ mean,  const float* __restrict__ var)
{
    const int tid = threadIdx.x;
    if (tid < C_) {
        const float inv = gamma[tid] * rsqrtf(var[tid] + 1e-5f);
        g_acoef[tid] = Ww[tid] * inv;
        g_dcoef[tid] = (Wb[tid] - mean[tid]) * inv + beta[tid];
    }
    if (tid < B_) {
        float s = 0.f;
        #pragma unroll
        for (int t = 0; t < NT1; t++) s += g_partial[tid * NT1 + t];
        g_s[tid] = s / (float)N_;
    }
}

// ---------------------------------------------------------------------------
// Kernel 3: z[b,c,n] = theta[b,n] * (s[b]*a[c]) + d[c] + x[b,c,n]
// One block per (b,c) row; theta row is L2-resident (reused C_=256 times).
// ---------------------------------------------------------------------------
__global__ __launch_bounds__(K3_THREADS)
void k3_epilogue(const float* __restrict__ x, float* __restrict__ z)
{
    const int c = blockIdx.x;
    const int b = blockIdx.y;
    const float coef = g_s[b] * g_acoef[c];
    const float dof  = g_dcoef[c];

    const size_t row = ((size_t)b * C_ + c) * N4;
    const float4* xr = reinterpret_cast<const float4*>(x) + row;
    float4*       zr = reinterpret_cast<float4*>(z) + row;
    const float4* th = reinterpret_cast<const float4*>(g_theta) + (size_t)b * N4;

    #pragma unroll
    for (int k = 0; k < 3; k++) {
        const int i = k * K3_THREADS + threadIdx.x;
        const float4 tv = __ldg(th + i);
        const float4 xv = __ldg(xr + i);
        float4 o;
        o.x = fmaf(tv.x, coef, dof) + xv.x;
        o.y = fmaf(tv.y, coef, dof) + xv.y;
        o.z = fmaf(tv.z, coef, dof) + xv.z;
        o.w = fmaf(tv.w, coef, dof) + xv.w;
        zr[i] = o;
    }
}

// ---------------------------------------------------------------------------
extern "C" void kernel_launch(void* const* d_in, const int* in_sizes, int n_in,
                              void* d_out, int out_size)
{
    const float* x     = (const float*)d_in[0];
    const float* g_w   = (const float*)d_in[1];
    const float* g_b   = (const float*)d_in[2];
    const float* th_w  = (const float*)d_in[3];
    const float* th_b  = (const float*)d_in[4];
    const float* ph_w  = (const float*)d_in[5];
    const float* ph_b  = (const float*)d_in[6];
    const float* W_w   = (const float*)d_in[7];
    const float* W_b   = (const float*)d_in[8];
    const float* gamma = (const float*)d_in[9];
    const float* beta  = (const float*)d_in[10];
    const float* mean  = (const float*)d_in[11];
    const float* var   = (const float*)d_in[12];
    float* z = (float*)d_out;

    dim3 g1(NT1, B_);
    k1_dots<<<g1, K1_THREADS>>>(x, g_w, g_b, th_w, th_b, ph_w, ph_b);

    k2_coeffs<<<1, 256>>>(W_w, W_b, gamma, beta, mean, var);

    dim3 g3(C_, B_);
    k3_epilogue<<<g3, K3_THREADS>>>(x, z);
}

// round 2
// speedup vs baseline: 1.2506x; 1.2506x over previous
#include <cuda_runtime.h>

// Fixed problem shape
constexpr int B_  = 32;
constexpr int C_  = 256;
constexpr int N_  = 4608;         // 96*48
constexpr int N4  = N_ / 4;

// Batch split for L2 producer->consumer reuse (75.5 MB/half < L2)
constexpr int SPLITS = 2;
constexpr int BH     = B_ / SPLITS;   // 16 batches per split

// k1: scalar mapping, one n per thread
constexpr int K1_THREADS = 128;
constexpr int NT1        = N_ / K1_THREADS;   // 36 tiles per batch
constexpr int K1_UNROLL  = 16;

constexpr int K3_THREADS = 384;               // 1152 float4 / 3 per thread

// Scratch (__device__ globals: allocation-free rule)
__device__ float g_theta[B_ * N_];
__device__ float g_partial[B_ * NT1];
__device__ float g_s[B_];
__device__ float g_acoef[C_];
__device__ float g_dcoef[C_];

// ---------------------------------------------------------------------------
// Kernel 1: per (b,n) channel dots (scalar n per thread, batched loads).
// ---------------------------------------------------------------------------
__global__ __launch_bounds__(K1_THREADS)
void k1_dots(const float* __restrict__ x,
             const float* __restrict__ gw, const float* __restrict__ gb,
             const float* __restrict__ tw, const float* __restrict__ tb,
             const float* __restrict__ pw, const float* __restrict__ pb,
             int bbase)
{
    __shared__ float swt[3 * C_];
    const int tid = threadIdx.x;
    for (int i = tid; i < C_; i += K1_THREADS) {
        swt[i]          = gw[i];
        swt[C_ + i]     = tw[i];
        swt[2 * C_ + i] = pw[i];
    }
    __syncthreads();

    const int t = blockIdx.x;
    const int b = bbase + blockIdx.y;
    const int n = t * K1_THREADS + tid;

    const float* xr = x + (size_t)b * C_ * N_ + n;

    float ga = 0.f, ta = 0.f, pa = 0.f;

    #pragma unroll
    for (int c0 = 0; c0 < C_; c0 += K1_UNROLL) {
        float xv[K1_UNROLL];
        #pragma unroll
        for (int j = 0; j < K1_UNROLL; j++)
            xv[j] = __ldg(xr + (size_t)(c0 + j) * N_);
        #pragma unroll
        for (int j = 0; j < K1_UNROLL; j++) {
            const int c = c0 + j;
            ga = fmaf(swt[c],          xv[j], ga);
            ta = fmaf(swt[C_ + c],     xv[j], ta);
            pa = fmaf(swt[2 * C_ + c], xv[j], pa);
        }
    }

    const float gb0 = __ldg(gb), tb0 = __ldg(tb), pb0 = __ldg(pb);

    float pg = (pa + pb0) * (ga + gb0);

    g_theta[(size_t)b * N_ + n] = ta + tb0;

    // block reduce pg
    #pragma unroll
    for (int off = 16; off > 0; off >>= 1)
        pg += __shfl_xor_sync(0xffffffffu, pg, off);

    __shared__ float red[K1_THREADS / 32];
    if ((tid & 31) == 0) red[tid >> 5] = pg;
    __syncthreads();
    if (tid == 0) {
        float s = 0.f;
        #pragma unroll
        for (int w = 0; w < K1_THREADS / 32; w++) s += red[w];
        g_partial[b * NT1 + t] = s;
    }
}

// ---------------------------------------------------------------------------
// Kernel 2 (tiny): s[b] for this split's batches; fold BN+W into a[c], d[c].
// ---------------------------------------------------------------------------
__global__ void k2_coeffs(const float* __restrict__ Ww, const float* __restrict__ Wb,
                          const float* __restrict__ gamma, const float* __restrict__ beta,
                          const float* __restrict__ mean,  const float* __restrict__ var,
                          int bbase)
{
    const int tid = threadIdx.x;
    if (tid < C_) {
        const float inv = gamma[tid] * rsqrtf(var[tid] + 1e-5f);
        g_acoef[tid] = Ww[tid] * inv;
        g_dcoef[tid] = (Wb[tid] - mean[tid]) * inv + beta[tid];
    }
    if (tid < BH) {
        const int b = bbase + tid;
        float s = 0.f;
        #pragma unroll
        for (int t = 0; t < NT1; t++) s += g_partial[b * NT1 + t];
        g_s[b] = s / (float)N_;
    }
}

// ---------------------------------------------------------------------------
// Kernel 3: z = theta[b,n]*(s[b]*a[c]) + d[c] + x[b,c,n]
// x read with last-use hint (L2 hit from k1 of same split); z streamed out.
// ---------------------------------------------------------------------------
__global__ __launch_bounds__(K3_THREADS)
void k3_epilogue(const float* __restrict__ x, float* __restrict__ z, int bbase)
{
    const int c = blockIdx.x;
    const int b = bbase + blockIdx.y;
    const float coef = g_s[b] * g_acoef[c];
    const float dof  = g_dcoef[c];

    const size_t row = ((size_t)b * C_ + c) * N4;
    const float4* xr = reinterpret_cast<const float4*>(x) + row;
    float4*       zr = reinterpret_cast<float4*>(z) + row;
    const float4* th = reinterpret_cast<const float4*>(g_theta) + (size_t)b * N4;

    #pragma unroll
    for (int k = 0; k < 3; k++) {
        const int i = k * K3_THREADS + threadIdx.x;
        const float4 tv = __ldg(th + i);
        const float4 xv = __ldcs(xr + i);     // last use of x: evict-first
        float4 o;
        o.x = fmaf(tv.x, coef, dof) + xv.x;
        o.y = fmaf(tv.y, coef, dof) + xv.y;
        o.z = fmaf(tv.z, coef, dof) + xv.z;
        o.w = fmaf(tv.w, coef, dof) + xv.w;
        __stcs(zr + i, o);                    // streaming store: don't pollute L2
    }
}

// ---------------------------------------------------------------------------
extern "C" void kernel_launch(void* const* d_in, const int* in_sizes, int n_in,
                              void* d_out, int out_size)
{
    const float* x     = (const float*)d_in[0];
    const float* g_w   = (const float*)d_in[1];
    const float* g_b   = (const float*)d_in[2];
    const float* th_w  = (const float*)d_in[3];
    const float* th_b  = (const float*)d_in[4];
    const float* ph_w  = (const float*)d_in[5];
    const float* ph_b  = (const float*)d_in[6];
    const float* W_w   = (const float*)d_in[7];
    const float* W_b   = (const float*)d_in[8];
    const float* gamma = (const float*)d_in[9];
    const float* beta  = (const float*)d_in[10];
    const float* mean  = (const float*)d_in[11];
    const float* var   = (const float*)d_in[12];
    float* z = (float*)d_out;

    for (int h = 0; h < SPLITS; h++) {
        const int bbase = h * BH;
        dim3 g1(NT1, BH);
        k1_dots<<<g1, K1_THREADS>>>(x, g_w, g_b, th_w, th_b, ph_w, ph_b, bbase);
        k2_coeffs<<<1, 256>>>(W_w, W_b, gamma, beta, mean, var, bbase);
        dim3 g3(C_, BH);
        k3_epilogue<<<g3, K3_THREADS>>>(x, z, bbase);
    }
}